// round 6
// baseline (speedup 1.0000x reference)
#include <cuda_runtime.h>
#include <cuda_bf16.h>

// BSplineNN: out[b,c] = sum_n coef[b,n,c] * B_{n,3}(x_b)
// B=4096, n=64, C=256, K=3, T=68.
// TWO batch rows per warp, software-pipelined:
//   phase 1: issue span-search knot loads for BOTH rows (one round trip)
//   phase 2: ballots -> spans j0, j1 -> issue 16x LDG.128 coef loads
//   phase 3: closed-form cubic weights for both rows under load latency
//   phase 4: FMA + STG.128
// Interior spans: guard-free closed form (all denominators contain
// [t[j], t[j+1]] > 0). Edge spans: fully-guarded reference recurrence.

#define NB    4096
#define NCOEF 64
#define NCH   256
#define NT    68
#define WARPS_PER_BLOCK 4
#define ROWS_PER_WARP   2

__device__ __forceinline__ float gdiv(float a, float d) {
    return (d == 0.0f) ? 0.0f : __fdividef(a, d);
}

__device__ __forceinline__ void compute_weights(const float* __restrict__ kt,
                                                float x, int j,
                                                float& w0, float& w1,
                                                float& w2, float& w3) {
    if (j >= 3 && j <= NCOEF - 1) {
        // Interior fast path; knots t[j-2..j+3] (L1 hits). No guards needed:
        // t[j] <= x < t[j+1] implies every denominator > 0.
        float t0 = __ldg(kt + j - 2);
        float t1 = __ldg(kt + j - 1);
        float t2 = __ldg(kt + j);
        float t3 = __ldg(kt + j + 1);
        float t4 = __ldg(kt + j + 2);
        float t5 = __ldg(kt + j + 3);

        float i1  = __fdividef(1.0f, t3 - t2);
        float b1m = (t3 - x) * i1;
        float b1c = (x - t2) * i1;

        float i20 = __fdividef(1.0f, t3 - t1);
        float i21 = __fdividef(1.0f, t4 - t2);
        float b2a = (t3 - x) * i20 * b1m;
        float b2b = (x - t1) * i20 * b1m + (t4 - x) * i21 * b1c;
        float b2c = (x - t2) * i21 * b1c;

        float i30 = __fdividef(1.0f, t3 - t0);
        float i31 = __fdividef(1.0f, t4 - t1);
        float i32 = __fdividef(1.0f, t5 - t2);
        w0 = (t3 - x) * i30 * b2a;
        w1 = (x - t0) * i30 * b2a + (t4 - x) * i31 * b2b;
        w2 = (x - t1) * i31 * b2b + (t5 - x) * i32 * b2c;
        w3 = (x - t2) * i32 * b2c;
    } else {
        w0 = w1 = w2 = w3 = 0.f;
        if (j >= 0) {
            float tv[8];
            #pragma unroll
            for (int m = 0; m < 8; m++) {
                int i = j - 3 + m;
                tv[m] = __ldg(kt + min(max(i, 0), NT - 1));
            }
            #define TV(i) tv[(i) - (j - 3)]
            float B1[4];
            #pragma unroll
            for (int q = 0; q < 4; q++) {
                int i = j - 2 + q;
                float v = 0.f;
                if (i >= 0 && i <= NT - 3) {
                    if (i == j)     v += gdiv(x - TV(i),     TV(i + 1) - TV(i));
                    if (i + 1 == j) v += gdiv(TV(i + 2) - x, TV(i + 2) - TV(i + 1));
                }
                B1[q] = v;
            }
            float B2[5];
            #pragma unroll
            for (int q = 0; q < 5; q++) {
                int i = j - 3 + q;
                float v = 0.f;
                if (i >= 0 && i <= NT - 4) {
                    float a1 = gdiv(x - TV(i),     TV(i + 2) - TV(i));
                    float a2 = gdiv(TV(i + 3) - x, TV(i + 3) - TV(i + 1));
                    float u1 = (q >= 1) ? B1[q - 1] : 0.f;
                    float u2 = (q <= 3) ? B1[q]     : 0.f;
                    v = a1 * u1 + a2 * u2;
                }
                B2[q] = v;
            }
            float wq[4];
            #pragma unroll
            for (int q = 0; q < 4; q++) {
                int n = j - 3 + q;
                float v = 0.f;
                if (n >= 0 && n <= NT - 5) {
                    float a1 = gdiv(x - TV(n),     TV(n + 3) - TV(n));
                    float a2 = gdiv(TV(n + 4) - x, TV(n + 4) - TV(n + 1));
                    v = a1 * B2[q] + a2 * B2[q + 1];
                }
                wq[q] = v;
            }
            w0 = wq[0]; w1 = wq[1]; w2 = wq[2]; w3 = wq[3];
            #undef TV
        }
    }
}

__global__ __launch_bounds__(WARPS_PER_BLOCK * 32)
void bspline_kernel(const float* __restrict__ coef,   // [B, 64, 256]
                    const float* __restrict__ knots,  // [B, 68]
                    const float* __restrict__ inpce,  // [B, 1]
                    float* __restrict__ out)          // [B, 256]
{
    const int lane = threadIdx.x & 31;
    const int wid  = blockIdx.x * WARPS_PER_BLOCK + (threadIdx.x >> 5);
    const int b0   = wid * ROWS_PER_WARP;
    const int b1   = b0 + 1;

    const float* kt0 = knots + b0 * NT;
    const float* kt1 = knots + b1 * NT;

    // ---- phase 1: issue all span-search loads for BOTH rows ----
    const float x0 = __ldg(inpce + b0);
    const float x1 = __ldg(inpce + b1);

    float p0a = __ldg(kt0 + lane),      p0b = __ldg(kt0 + lane + 1);
    float p0c = __ldg(kt0 + lane + 32), p0d = __ldg(kt0 + lane + 33);
    float p1a = __ldg(kt1 + lane),      p1b = __ldg(kt1 + lane + 1);
    float p1c = __ldg(kt1 + lane + 32), p1d = __ldg(kt1 + lane + 33);
    bool tl = (lane < 3);
    float p0e = tl ? __ldg(kt0 + lane + 64) : 0.f;
    float p0f = tl ? __ldg(kt0 + lane + 65) : 0.f;
    float p1e = tl ? __ldg(kt1 + lane + 64) : 0.f;
    float p1f = tl ? __ldg(kt1 + lane + 65) : 0.f;

    // ---- phase 2: ballots -> spans ----
    unsigned m01 = __ballot_sync(0xffffffffu, (p0a <= x0) & (x0 < p0b));
    unsigned m02 = __ballot_sync(0xffffffffu, (p0c <= x0) & (x0 < p0d));
    unsigned m03 = __ballot_sync(0xffffffffu, tl & (p0e <= x0) & (x0 < p0f));
    unsigned m11 = __ballot_sync(0xffffffffu, (p1a <= x1) & (x1 < p1b));
    unsigned m12 = __ballot_sync(0xffffffffu, (p1c <= x1) & (x1 < p1d));
    unsigned m13 = __ballot_sync(0xffffffffu, tl & (p1e <= x1) & (x1 < p1f));

    const int j0 = m01 ? (__ffs(m01) - 1) : m02 ? (31 + __ffs(m02)) : m03 ? (63 + __ffs(m03)) : -1;
    const int j1 = m11 ? (__ffs(m11) - 1) : m12 ? (31 + __ffs(m12)) : m13 ? (63 + __ffs(m13)) : -1;

    // ---- issue all 16 coefficient LDG.128 (addresses only need spans) ----
    const int jc0 = (j0 < 0) ? 3 : j0;
    const int jc1 = (j1 < 0) ? 3 : j1;

    const float4* cr0 = (const float4*)(coef + (long long)b0 * (NCOEF * NCH));
    const float4* cr1 = (const float4*)(coef + (long long)b1 * (NCOEF * NCH));

    float4 r0[8], r1[8];
    #pragma unroll
    for (int q = 0; q < 4; q++) {
        int n0 = min(max(jc0 - 3 + q, 0), NCOEF - 1);
        r0[2 * q]     = __ldg(cr0 + n0 * 64 + lane);
        r0[2 * q + 1] = __ldg(cr0 + n0 * 64 + lane + 32);
    }
    #pragma unroll
    for (int q = 0; q < 4; q++) {
        int n1 = min(max(jc1 - 3 + q, 0), NCOEF - 1);
        r1[2 * q]     = __ldg(cr1 + n1 * 64 + lane);
        r1[2 * q + 1] = __ldg(cr1 + n1 * 64 + lane + 32);
    }

    // ---- phase 3: weights for both rows (under coef-load latency) ----
    float u0, u1, u2, u3, v0, v1, v2, v3;
    compute_weights(kt0, x0, j0, u0, u1, u2, u3);
    compute_weights(kt1, x1, j1, v0, v1, v2, v3);

    // ---- phase 4: combine + store ----
    float4 a;
    float4* o0 = (float4*)(out + (long long)b0 * NCH);
    a.x = u0 * r0[0].x + u1 * r0[2].x + u2 * r0[4].x + u3 * r0[6].x;
    a.y = u0 * r0[0].y + u1 * r0[2].y + u2 * r0[4].y + u3 * r0[6].y;
    a.z = u0 * r0[0].z + u1 * r0[2].z + u2 * r0[4].z + u3 * r0[6].z;
    a.w = u0 * r0[0].w + u1 * r0[2].w + u2 * r0[4].w + u3 * r0[6].w;
    o0[lane] = a;
    a.x = u0 * r0[1].x + u1 * r0[3].x + u2 * r0[5].x + u3 * r0[7].x;
    a.y = u0 * r0[1].y + u1 * r0[3].y + u2 * r0[5].y + u3 * r0[7].y;
    a.z = u0 * r0[1].z + u1 * r0[3].z + u2 * r0[5].z + u3 * r0[7].z;
    a.w = u0 * r0[1].w + u1 * r0[3].w + u2 * r0[5].w + u3 * r0[7].w;
    o0[lane + 32] = a;

    float4* o1 = (float4*)(out + (long long)b1 * NCH);
    a.x = v0 * r1[0].x + v1 * r1[2].x + v2 * r1[4].x + v3 * r1[6].x;
    a.y = v0 * r1[0].y + v1 * r1[2].y + v2 * r1[4].y + v3 * r1[6].y;
    a.z = v0 * r1[0].z + v1 * r1[2].z + v2 * r1[4].z + v3 * r1[6].z;
    a.w = v0 * r1[0].w + v1 * r1[2].w + v2 * r1[4].w + v3 * r1[6].w;
    o1[lane] = a;
    a.x = v0 * r1[1].x + v1 * r1[3].x + v2 * r1[5].x + v3 * r1[7].x;
    a.y = v0 * r1[1].y + v1 * r1[3].y + v2 * r1[5].y + v3 * r1[7].y;
    a.z = v0 * r1[1].z + v1 * r1[3].z + v2 * r1[5].z + v3 * r1[7].z;
    a.w = v0 * r1[1].w + v1 * r1[3].w + v2 * r1[5].w + v3 * r1[7].w;
    o1[lane + 32] = a;
}

extern "C" void kernel_launch(void* const* d_in, const int* in_sizes, int n_in,
                              void* d_out, int out_size) {
    const float* coef  = (const float*)d_in[0];  // [4096, 64, 256]
    const float* knots = (const float*)d_in[1];  // [4096, 68]
    const float* inpce = (const float*)d_in[2];  // [4096, 1]
    float* out = (float*)d_out;                  // [4096, 256]

    const int rows_per_block = WARPS_PER_BLOCK * ROWS_PER_WARP;
    bspline_kernel<<<NB / rows_per_block, WARPS_PER_BLOCK * 32>>>(coef, knots, inpce, out);
}

// round 7
// speedup vs baseline: 1.0072x; 1.0072x over previous
#include <cuda_runtime.h>
#include <cuda_bf16.h>

// BSplineNN: out[b,c] = sum_n coef[b,n,c] * B_{n,3}(x_b)
// B=4096, n=64, C=256, K=3, T=68.
// TWO warps per batch row (each: 128 channels, 4x LDG.128/lane) -> 8192
// warps (~55/SM) for latency hiding. Weight math is the cheap closed form
// (R5), so duplicating it across the row's two warps costs ~40 instr.
// Span j via ballots -> issue coef loads immediately -> weights under
// load latency -> FMA -> STG.128.

#define NB    4096
#define NCOEF 64
#define NCH   256
#define NT    68
#define WARPS_PER_BLOCK 8
#define ROWS_PER_BLOCK  4   // 2 warps per row

__device__ __forceinline__ float gdiv(float a, float d) {
    return (d == 0.0f) ? 0.0f : __fdividef(a, d);
}

__global__ __launch_bounds__(WARPS_PER_BLOCK * 32)
void bspline_kernel(const float* __restrict__ coef,   // [B, 64, 256]
                    const float* __restrict__ knots,  // [B, 68]
                    const float* __restrict__ inpce,  // [B, 1]
                    float* __restrict__ out)          // [B, 256]
{
    const int warp = threadIdx.x >> 5;
    const int lane = threadIdx.x & 31;
    const int b    = blockIdx.x * ROWS_PER_BLOCK + (warp >> 1);
    const int half = warp & 1;

    const float* kt = knots + b * NT;
    const float  x  = __ldg(inpce + b);    // broadcast

    // ---- span search: indicator t[i] <= x < t[i+1], i in [0, 66] ----
    bool c1 = (__ldg(kt + lane)      <= x) & (x < __ldg(kt + lane + 1));
    bool c2 = (__ldg(kt + lane + 32) <= x) & (x < __ldg(kt + lane + 33));
    bool c3 = (lane < 3) && (__ldg(kt + lane + 64) <= x) && (x < __ldg(kt + lane + 65));
    unsigned m1 = __ballot_sync(0xffffffffu, c1);
    unsigned m2 = __ballot_sync(0xffffffffu, c2);
    unsigned m3 = __ballot_sync(0xffffffffu, c3);
    const int j = m1 ? (__ffs(m1) - 1)
                : m2 ? (31 + __ffs(m2))
                : m3 ? (63 + __ffs(m3))
                : -1;

    // ---- issue coefficient loads NOW (addresses depend only on j) ----
    const int jc = (j < 0) ? 3 : j;
    const int n0 = min(max(jc - 3, 0), NCOEF - 1);
    const int n1 = min(max(jc - 2, 0), NCOEF - 1);
    const int n2 = min(max(jc - 1, 0), NCOEF - 1);
    const int n3 = min(max(jc,     0), NCOEF - 1);

    const float4* cr = (const float4*)(coef + (long long)b * (NCOEF * NCH));
    const int c4 = half * 32 + lane;               // float4 index within 64-float4 row

    float4 r0 = __ldg(cr + n0 * 64 + c4);
    float4 r1 = __ldg(cr + n1 * 64 + c4);
    float4 r2 = __ldg(cr + n2 * 64 + c4);
    float4 r3 = __ldg(cr + n3 * 64 + c4);

    // ---- weights (under coef-load latency; knot reloads hit L1) ----
    float w0, w1, w2, w3;
    if (j >= 3 && j <= NCOEF - 1) {
        // Interior fast path: t[j] <= x < t[j+1] implies every denominator
        // below is > 0, so no guards needed.
        float t0 = __ldg(kt + j - 2);
        float t1 = __ldg(kt + j - 1);
        float t2 = __ldg(kt + j);
        float t3 = __ldg(kt + j + 1);
        float t4 = __ldg(kt + j + 2);
        float t5 = __ldg(kt + j + 3);

        float i1  = __fdividef(1.0f, t3 - t2);
        float b1m = (t3 - x) * i1;
        float b1c = (x - t2) * i1;

        float i20 = __fdividef(1.0f, t3 - t1);
        float i21 = __fdividef(1.0f, t4 - t2);
        float b2a = (t3 - x) * i20 * b1m;
        float b2b = (x - t1) * i20 * b1m + (t4 - x) * i21 * b1c;
        float b2c = (x - t2) * i21 * b1c;

        float i30 = __fdividef(1.0f, t3 - t0);
        float i31 = __fdividef(1.0f, t4 - t1);
        float i32 = __fdividef(1.0f, t5 - t2);
        w0 = (t3 - x) * i30 * b2a;
        w1 = (x - t0) * i30 * b2a + (t4 - x) * i31 * b2b;
        w2 = (x - t1) * i31 * b2b + (t5 - x) * i32 * b2c;
        w3 = (x - t2) * i32 * b2c;
    } else {
        // Edge / out-of-range: fully guarded reference recurrence.
        w0 = w1 = w2 = w3 = 0.f;
        if (j >= 0) {
            float tv[8];
            #pragma unroll
            for (int m = 0; m < 8; m++) {
                int i = j - 3 + m;
                tv[m] = __ldg(kt + min(max(i, 0), NT - 1));
            }
            #define TV(i) tv[(i) - (j - 3)]
            float B1[4];
            #pragma unroll
            for (int q = 0; q < 4; q++) {
                int i = j - 2 + q;
                float v = 0.f;
                if (i >= 0 && i <= NT - 3) {
                    if (i == j)     v += gdiv(x - TV(i),     TV(i + 1) - TV(i));
                    if (i + 1 == j) v += gdiv(TV(i + 2) - x, TV(i + 2) - TV(i + 1));
                }
                B1[q] = v;
            }
            float B2[5];
            #pragma unroll
            for (int q = 0; q < 5; q++) {
                int i = j - 3 + q;
                float v = 0.f;
                if (i >= 0 && i <= NT - 4) {
                    float a1 = gdiv(x - TV(i),     TV(i + 2) - TV(i));
                    float a2 = gdiv(TV(i + 3) - x, TV(i + 3) - TV(i + 1));
                    float u1 = (q >= 1) ? B1[q - 1] : 0.f;
                    float u2 = (q <= 3) ? B1[q]     : 0.f;
                    v = a1 * u1 + a2 * u2;
                }
                B2[q] = v;
            }
            float wq[4];
            #pragma unroll
            for (int q = 0; q < 4; q++) {
                int n = j - 3 + q;
                float v = 0.f;
                if (n >= 0 && n <= NT - 5) {
                    float a1 = gdiv(x - TV(n),     TV(n + 3) - TV(n));
                    float a2 = gdiv(TV(n + 4) - x, TV(n + 4) - TV(n + 1));
                    v = a1 * B2[q] + a2 * B2[q + 1];
                }
                wq[q] = v;
            }
            w0 = wq[0]; w1 = wq[1]; w2 = wq[2]; w3 = wq[3];
            #undef TV
        }
    }

    // ---- combine + store ----
    float4 a;
    a.x = w0 * r0.x + w1 * r1.x + w2 * r2.x + w3 * r3.x;
    a.y = w0 * r0.y + w1 * r1.y + w2 * r2.y + w3 * r3.y;
    a.z = w0 * r0.z + w1 * r1.z + w2 * r2.z + w3 * r3.z;
    a.w = w0 * r0.w + w1 * r1.w + w2 * r2.w + w3 * r3.w;

    ((float4*)(out + (long long)b * NCH))[c4] = a;
}

extern "C" void kernel_launch(void* const* d_in, const int* in_sizes, int n_in,
                              void* d_out, int out_size) {
    const float* coef  = (const float*)d_in[0];  // [4096, 64, 256]
    const float* knots = (const float*)d_in[1];  // [4096, 68]
    const float* inpce = (const float*)d_in[2];  // [4096, 1]
    float* out = (float*)d_out;                  // [4096, 256]

    bspline_kernel<<<NB / ROWS_PER_BLOCK, WARPS_PER_BLOCK * 32>>>(coef, knots, inpce, out);
}

// round 8
// speedup vs baseline: 1.2977x; 1.2884x over previous
#include <cuda_runtime.h>
#include <cuda_bf16.h>

// BSplineNN: out[b,c] = sum_n coef[b,n,c] * B_{n,3}(x_b)
// B=4096, n=64, C=256, K=3, T=68.  One WARP per batch row.
// Chain-surgery version:
//  - span via count: lane l (l<=16) loads knots[4l..4l+3] with ONE LDG.128,
//    counts t<=x, warp __reduce_add -> j = count-1 (intervals partition,
//    so t[j]<=x<t[j+1] automatically; count 0 or 68 -> out of range).
//  - weight-window knot loads (L1 hits) issued BEFORE coef loads: the
//    per-SM L1tex queue is a FIFO (completion order = issue order), so
//    this is what actually lets the divide chain overlap coef DRAM latency.
//  - interior spans: guard-free closed form; edges: guarded recurrence.

#define NB    4096
#define NCOEF 64
#define NCH   256
#define NT    68
#define WARPS_PER_BLOCK 4

__device__ __forceinline__ float gdiv(float a, float d) {
    return (d == 0.0f) ? 0.0f : __fdividef(a, d);
}

__global__ __launch_bounds__(WARPS_PER_BLOCK * 32)
void bspline_kernel(const float* __restrict__ coef,   // [B, 64, 256]
                    const float* __restrict__ knots,  // [B, 68]
                    const float* __restrict__ inpce,  // [B, 1]
                    float* __restrict__ out)          // [B, 256]
{
    const int lane = threadIdx.x & 31;
    const int b    = blockIdx.x * WARPS_PER_BLOCK + (threadIdx.x >> 5);

    const float* kt = knots + b * NT;
    const float  x  = __ldg(inpce + b);    // broadcast

    // ---- phase A: one LDG.128 per lane covers all 68 knots ----
    float4 kv = __ldg((const float4*)kt + min(lane, 16));
    int cnt = 0;
    if (lane <= 16) {
        cnt = (kv.x <= x) + (kv.y <= x) + (kv.z <= x) + (kv.w <= x);
    }
    const int total = __reduce_add_sync(0xffffffffu, cnt);   // #knots <= x
    const int j     = total - 1;                             // span candidate
    const bool valid = (total >= 1 && total <= NT - 1);      // t[j]<=x<t[j+1]
    const int jc = valid ? j : 3;

    // ---- weight-window knot loads FIRST (L1 hits, front of LSU FIFO) ----
    float tv[8];
    #pragma unroll
    for (int m = 0; m < 8; m++) {
        tv[m] = __ldg(kt + min(max(jc - 3 + m, 0), NT - 1));   // tv[m] = t[jc-3+m]
    }

    // ---- coef loads (DRAM), addresses depend only on jc ----
    const int n0 = min(max(jc - 3, 0), NCOEF - 1);
    const int n1 = min(max(jc - 2, 0), NCOEF - 1);
    const int n2 = min(max(jc - 1, 0), NCOEF - 1);
    const int n3 = min(max(jc,     0), NCOEF - 1);

    const float4* cr = (const float4*)(coef + (long long)b * (NCOEF * NCH));
    float4 r00 = __ldg(cr + n0 * 64 + lane);
    float4 r01 = __ldg(cr + n0 * 64 + lane + 32);
    float4 r10 = __ldg(cr + n1 * 64 + lane);
    float4 r11 = __ldg(cr + n1 * 64 + lane + 32);
    float4 r20 = __ldg(cr + n2 * 64 + lane);
    float4 r21 = __ldg(cr + n2 * 64 + lane + 32);
    float4 r30 = __ldg(cr + n3 * 64 + lane);
    float4 r31 = __ldg(cr + n3 * 64 + lane + 32);

    // ---- weights from tv registers (overlaps coef DRAM latency) ----
    float w0 = 0.f, w1 = 0.f, w2 = 0.f, w3 = 0.f;
    if (valid && j >= 3 && j <= NCOEF - 1) {
        // Interior: tv has no clamp distortion (j-3..j+4 within [0,67]).
        // t[j] <= x < t[j+1] implies every denominator > 0: no guards.
        float t0 = tv[1];   // t[j-2]
        float t1 = tv[2];   // t[j-1]
        float t2 = tv[3];   // t[j]
        float t3 = tv[4];   // t[j+1]
        float t4 = tv[5];   // t[j+2]
        float t5 = tv[6];   // t[j+3]

        float i1  = __fdividef(1.0f, t3 - t2);
        float b1m = (t3 - x) * i1;
        float b1c = (x - t2) * i1;

        float i20 = __fdividef(1.0f, t3 - t1);
        float i21 = __fdividef(1.0f, t4 - t2);
        float b2a = (t3 - x) * i20 * b1m;
        float b2b = (x - t1) * i20 * b1m + (t4 - x) * i21 * b1c;
        float b2c = (x - t2) * i21 * b1c;

        float i30 = __fdividef(1.0f, t3 - t0);
        float i31 = __fdividef(1.0f, t4 - t1);
        float i32 = __fdividef(1.0f, t5 - t2);
        w0 = (t3 - x) * i30 * b2a;
        w1 = (x - t0) * i30 * b2a + (t4 - x) * i31 * b2b;
        w2 = (x - t1) * i31 * b2b + (t5 - x) * i32 * b2c;
        w3 = (x - t2) * i32 * b2c;
    } else if (valid) {
        // Edge spans: fully guarded reference recurrence on the tv window.
        #define TV(i) tv[(i) - (j - 3)]
        float B1[4];
        #pragma unroll
        for (int q = 0; q < 4; q++) {
            int i = j - 2 + q;
            float v = 0.f;
            if (i >= 0 && i <= NT - 3) {
                if (i == j)     v += gdiv(x - TV(i),     TV(i + 1) - TV(i));
                if (i + 1 == j) v += gdiv(TV(i + 2) - x, TV(i + 2) - TV(i + 1));
            }
            B1[q] = v;
        }
        float B2[5];
        #pragma unroll
        for (int q = 0; q < 5; q++) {
            int i = j - 3 + q;
            float v = 0.f;
            if (i >= 0 && i <= NT - 4) {
                float a1 = gdiv(x - TV(i),     TV(i + 2) - TV(i));
                float a2 = gdiv(TV(i + 3) - x, TV(i + 3) - TV(i + 1));
                float u1 = (q >= 1) ? B1[q - 1] : 0.f;
                float u2 = (q <= 3) ? B1[q]     : 0.f;
                v = a1 * u1 + a2 * u2;
            }
            B2[q] = v;
        }
        #pragma unroll
        for (int q = 0; q < 4; q++) {
            int n = j - 3 + q;
            float v = 0.f;
            if (n >= 0 && n <= NT - 5) {
                float a1 = gdiv(x - TV(n),     TV(n + 3) - TV(n));
                float a2 = gdiv(TV(n + 4) - x, TV(n + 4) - TV(n + 1));
                v = a1 * B2[q] + a2 * B2[q + 1];
            }
            if (q == 0) w0 = v; else if (q == 1) w1 = v;
            else if (q == 2) w2 = v; else w3 = v;
        }
        #undef TV
    }

    // ---- combine + store (256 channels per warp) ----
    float4 a0, a1;
    a0.x = w0 * r00.x + w1 * r10.x + w2 * r20.x + w3 * r30.x;
    a0.y = w0 * r00.y + w1 * r10.y + w2 * r20.y + w3 * r30.y;
    a0.z = w0 * r00.z + w1 * r10.z + w2 * r20.z + w3 * r30.z;
    a0.w = w0 * r00.w + w1 * r10.w + w2 * r20.w + w3 * r30.w;
    a1.x = w0 * r01.x + w1 * r11.x + w2 * r21.x + w3 * r31.x;
    a1.y = w0 * r01.y + w1 * r11.y + w2 * r21.y + w3 * r31.y;
    a1.z = w0 * r01.z + w1 * r11.z + w2 * r21.z + w3 * r31.z;
    a1.w = w0 * r01.w + w1 * r11.w + w2 * r21.w + w3 * r31.w;

    float4* o = (float4*)(out + (long long)b * NCH);
    o[lane]      = a0;
    o[lane + 32] = a1;
}

extern "C" void kernel_launch(void* const* d_in, const int* in_sizes, int n_in,
                              void* d_out, int out_size) {
    const float* coef  = (const float*)d_in[0];  // [4096, 64, 256]
    const float* knots = (const float*)d_in[1];  // [4096, 68]
    const float* inpce = (const float*)d_in[2];  // [4096, 1]
    float* out = (float*)d_out;                  // [4096, 256]

    bspline_kernel<<<NB / WARPS_PER_BLOCK, WARPS_PER_BLOCK * 32>>>(coef, knots, inpce, out);
}